// round 2
// baseline (speedup 1.0000x reference)
#include <cuda_runtime.h>
#include <math.h>

#define NN     4096
#define BB     8
#define NPG    512
#define KK     30
#define NBASIS 32
#define EDIM   35      // NBASIS + 3
#define HH     256
#define X2H    512
#define TT     128
#define LL     5
#define RADIUS 1.5f

// ---------------- static scratch (no allocations allowed) ----------------
__device__ __align__(16) float d_tfeat[BB * TT];
__device__ __align__(16) float d_tproj[LL * BB * HH];
__device__ __align__(16) float d_h[NN * HH];
__device__ __align__(16) float d_x[NN * X2H];
__device__ __align__(16) float d_aggr[NN * X2H];
__device__ __align__(16) float d_z1[NN * HH];
__device__ __align__(16) float d_z[NN * HH];
__device__ __align__(16) float d_eattr[NN * KK * 36];   // padded to 36, [..][35]=0
__device__ int   d_nbr[NN * KK];
__device__ int   d_cnt[NN];
__device__ __align__(16) float d_sumz[BB * HH];
__device__ __align__(16) float d_sumc2[BB * HH];

__device__ __forceinline__ float silu_f(float v) { return v / (1.f + expf(-v)); }

// ---------------- time embedding: GFP + Linear + SiLU -> t_feat [B,T] ----
__global__ void k_temb(const float* __restrict__ tin, const float* __restrict__ wgfp,
                       const float* __restrict__ wt, const float* __restrict__ bt) {
    __shared__ float ss[64], sc[64];
    int t = threadIdx.x; // 128 threads
    for (int b = 0; b < BB; b++) {
        if (t < 64) {
            float xp = 6.283185307179586f * tin[b] * wgfp[t];
            ss[t] = sinf(xp);
            sc[t] = cosf(xp);
        }
        __syncthreads();
        float acc = bt[t];
        #pragma unroll 8
        for (int h = 0; h < 64; h++) {
            acc = fmaf(ss[h], wt[h * TT + t], acc);
            acc = fmaf(sc[h], wt[(64 + h) * TT + t], acc);
        }
        d_tfeat[b * TT + t] = silu_f(acc);
        __syncthreads();
    }
}

// ---------------- per-layer time projection: tproj[l][b][:] = t_feat@Wt[l]+bt[l]
__global__ void k_tproj(const float* __restrict__ Wt, const float* __restrict__ bt) {
    int l = blockIdx.x / BB, b = blockIdx.x % BB;
    int c = threadIdx.x; // 256
    __shared__ float tf[TT];
    if (c < TT) tf[c] = d_tfeat[b * TT + c];
    __syncthreads();
    float acc = bt[l * HH + c];
    const float* w = Wt + (size_t)l * TT * HH;
    #pragma unroll 8
    for (int k = 0; k < TT; k++) acc = fmaf(tf[k], w[k * HH + c], acc);
    d_tproj[(l * BB + b) * HH + c] = acc;
}

// ---------------- h0 = coords @ W_in + b_in -------------------------------
__global__ void k_hin(const float* __restrict__ coords, const float* __restrict__ Win,
                      const float* __restrict__ bin) {
    int i = blockIdx.x;
    int c = threadIdx.x;
    float x0 = coords[i * 3 + 0], x1 = coords[i * 3 + 1], x2 = coords[i * 3 + 2];
    float v = fmaf(x0, Win[c], fmaf(x1, Win[HH + c], fmaf(x2, Win[2 * HH + c], bin[c])));
    d_h[(size_t)i * HH + c] = v;
}

// ---------------- radius graph: K nearest within R, warp per node ---------
__global__ void __launch_bounds__(128) k_nbr(const float* __restrict__ coords) {
    __shared__ float sx[NPG], sy[NPG], sz[NPG];
    __shared__ float sd[4][NPG];
    int t = threadIdx.x;
    int base = blockIdx.x * 4;           // 4 nodes per block, same graph
    int g = base >> 9;
    int goff = g << 9;
    for (int j = t; j < NPG; j += 128) {
        sx[j] = coords[(goff + j) * 3 + 0];
        sy[j] = coords[(goff + j) * 3 + 1];
        sz[j] = coords[(goff + j) * 3 + 2];
    }
    __syncthreads();
    int w = t >> 5, lane = t & 31;
    int il = (base & 511) + w;           // local node index within graph
    int ig = goff + il;                  // global node index
    float xi = sx[il], yi = sy[il], zi = sz[il];
    float sqi = xi * xi + yi * yi + zi * zi;
    for (int j = lane; j < NPG; j += 32) {
        float xj = sx[j], yj = sy[j], zj = sz[j];
        float dot = xi * xj + yi * yj + zi * zj;
        float sqj = xj * xj + yj * yj + zj * zj;
        float d2 = sqi + sqj - 2.f * dot;
        float d = sqrtf(fmaxf(d2, 1e-12f));
        sd[w][j] = (j != il && d < RADIUS) ? d : INFINITY;
    }
    __syncwarp();
    int cc = 0;
    for (int k = 0; k < KK; k++) {
        float best = INFINITY;
        int bi = -1;
        for (int j = lane; j < NPG; j += 32) {
            float v = sd[w][j];
            if (v < best) { best = v; bi = j; }
        }
        #pragma unroll
        for (int off = 16; off; off >>= 1) {
            float ov = __shfl_down_sync(0xffffffffu, best, off);
            int oi = __shfl_down_sync(0xffffffffu, bi, off);
            if (ov < best || (ov == best && (unsigned)oi < (unsigned)bi)) { best = ov; bi = oi; }
        }
        best = __shfl_sync(0xffffffffu, best, 0);
        bi = __shfl_sync(0xffffffffu, bi, 0);
        if (!(best < INFINITY)) break;
        if (lane == 0) {
            d_nbr[ig * KK + k] = goff + bi;
            sd[w][bi] = INFINITY;
        }
        cc = k + 1;
        __syncwarp();
    }
    if (lane == 0) d_cnt[ig] = cc;
}

// ---------------- edge attributes: gaussian basis + unit dir -------------
__global__ void k_eattr(const float* __restrict__ coords) {
    int e = blockIdx.x * blockDim.x + threadIdx.x;
    if (e >= NN * KK) return;
    int i = e / KK, k = e % KK;
    float* o = d_eattr + (size_t)e * 36;
    o[35] = 0.f;
    if (k >= d_cnt[i]) return;
    int s = d_nbr[e];
    float ex = coords[s * 3 + 0] - coords[i * 3 + 0];
    float ey = coords[s * 3 + 1] - coords[i * 3 + 1];
    float ez = coords[s * 3 + 2] - coords[i * 3 + 2];
    float d2 = ex * ex + ey * ey + ez * ez;
    float el = sqrtf(fmaxf(d2, 1e-12f));
    float inv = 1.f / el;
    const float step = RADIUS / 33.f;
    const float istep = 33.f / RADIUS;
    #pragma unroll
    for (int m = 0; m < NBASIS; m++) {
        float dd = (el - (float)(m + 1) * step) * istep;
        o[m] = expf(-dd * dd) * (1.f / 1.12f);
    }
    o[32] = ex * inv;
    o[33] = ey * inv;
    o[34] = ez * inv;
}

// ---------------- x = concat(h, tproj[l][batch]) -------------------------
__global__ void k_x(int l) {
    int idx = blockIdx.x * 256 + threadIdx.x;
    int i = idx >> 9, c = idx & 511;
    float v;
    if (c < HH) v = d_h[(size_t)i * HH + c];
    else        v = d_tproj[(l * BB + (i >> 9)) * HH + (c - HH)];
    d_x[idx] = v;
}

// ---------------- GINE message + aggregate: aggr[i] = sum_k relu(x[src]+ea)
__global__ void __launch_bounds__(256) k_edge(const float* __restrict__ We,
                                              const float* __restrict__ be) {
    int i = blockIdx.x;
    int t = threadIdx.x;
    __shared__ float sea[KK][36];
    __shared__ int snbr[KK];
    int count = d_cnt[i];
    const float* ge = d_eattr + (size_t)i * KK * 36;
    for (int e = t; e < count * 36; e += 256) sea[e / 36][e % 36] = ge[e];
    if (t < KK && t < count) snbr[t] = d_nbr[i * KK + t];
    int c0 = t, c1 = t + 256;
    float w0[36], w1[36];
    #pragma unroll
    for (int m = 0; m < EDIM; m++) { w0[m] = We[m * X2H + c0]; w1[m] = We[m * X2H + c1]; }
    w0[35] = 0.f; w1[35] = 0.f;
    float b0 = be[c0], b1 = be[c1];
    __syncthreads();
    float a0 = 0.f, a1 = 0.f;
    for (int k = 0; k < count; k++) {
        int s = snbr[k];
        float xs0 = d_x[(size_t)s * X2H + c0];
        float xs1 = d_x[(size_t)s * X2H + c1];
        float t0 = b0, t1 = b1;
        const float4* er = (const float4*)sea[k];
        #pragma unroll
        for (int m4 = 0; m4 < 9; m4++) {
            float4 e4 = er[m4];
            t0 = fmaf(e4.x, w0[m4 * 4 + 0], t0); t1 = fmaf(e4.x, w1[m4 * 4 + 0], t1);
            t0 = fmaf(e4.y, w0[m4 * 4 + 1], t0); t1 = fmaf(e4.y, w1[m4 * 4 + 1], t1);
            t0 = fmaf(e4.z, w0[m4 * 4 + 2], t0); t1 = fmaf(e4.z, w1[m4 * 4 + 2], t1);
            t0 = fmaf(e4.w, w0[m4 * 4 + 3], t0); t1 = fmaf(e4.w, w1[m4 * 4 + 3], t1);
        }
        a0 += fmaxf(xs0 + t0, 0.f);
        a1 += fmaxf(xs1 + t1, 0.f);
    }
    d_aggr[(size_t)i * X2H + c0] = a0;
    d_aggr[(size_t)i * X2H + c1] = a1;
}

// ---------------- tiled GEMM: MODE0 z1=silu(((1+eps)x+aggr)@W1+b1), MODE1 z=z1@W2+b2
template <int MODE>
__global__ void __launch_bounds__(256) k_gemm(const float* __restrict__ Bw,
                                              const float* __restrict__ bias,
                                              const float* __restrict__ epsp, int l) {
    const int Kd = (MODE == 0) ? X2H : HH;
    const int Nd = HH;
    __shared__ float As[16][64];
    __shared__ float Bs[16][64];
    int t = threadIdx.x;
    int m0 = blockIdx.y * 64, n0 = blockIdx.x * 64;
    int ty = t >> 4, tx = t & 15;
    int ar = t >> 2, akc = (t & 3) * 4;
    int br = t >> 4, bnc = (t & 15) * 4;
    float ep = (MODE == 0) ? (1.f + epsp[l]) : 0.f;
    const float* A = (MODE == 0) ? d_x : d_z1;
    float* C = (MODE == 0) ? d_z1 : d_z;
    float acc[4][4];
    #pragma unroll
    for (int i = 0; i < 4; i++)
        #pragma unroll
        for (int j = 0; j < 4; j++) acc[i][j] = 0.f;
    for (int k0 = 0; k0 < Kd; k0 += 16) {
        float4 av = *(const float4*)(A + (size_t)(m0 + ar) * Kd + k0 + akc);
        if (MODE == 0) {
            float4 g4 = *(const float4*)(d_aggr + (size_t)(m0 + ar) * Kd + k0 + akc);
            av.x = fmaf(ep, av.x, g4.x);
            av.y = fmaf(ep, av.y, g4.y);
            av.z = fmaf(ep, av.z, g4.z);
            av.w = fmaf(ep, av.w, g4.w);
        }
        As[akc + 0][ar] = av.x;
        As[akc + 1][ar] = av.y;
        As[akc + 2][ar] = av.z;
        As[akc + 3][ar] = av.w;
        *(float4*)&Bs[br][bnc] = *(const float4*)(Bw + (size_t)(k0 + br) * Nd + n0 + bnc);
        __syncthreads();
        #pragma unroll
        for (int kk = 0; kk < 16; kk++) {
            float4 a4 = *(const float4*)&As[kk][ty * 4];
            float4 b4 = *(const float4*)&Bs[kk][tx * 4];
            acc[0][0] = fmaf(a4.x, b4.x, acc[0][0]); acc[0][1] = fmaf(a4.x, b4.y, acc[0][1]);
            acc[0][2] = fmaf(a4.x, b4.z, acc[0][2]); acc[0][3] = fmaf(a4.x, b4.w, acc[0][3]);
            acc[1][0] = fmaf(a4.y, b4.x, acc[1][0]); acc[1][1] = fmaf(a4.y, b4.y, acc[1][1]);
            acc[1][2] = fmaf(a4.y, b4.z, acc[1][2]); acc[1][3] = fmaf(a4.y, b4.w, acc[1][3]);
            acc[2][0] = fmaf(a4.z, b4.x, acc[2][0]); acc[2][1] = fmaf(a4.z, b4.y, acc[2][1]);
            acc[2][2] = fmaf(a4.z, b4.z, acc[2][2]); acc[2][3] = fmaf(a4.z, b4.w, acc[2][3]);
            acc[3][0] = fmaf(a4.w, b4.x, acc[3][0]); acc[3][1] = fmaf(a4.w, b4.y, acc[3][1]);
            acc[3][2] = fmaf(a4.w, b4.z, acc[3][2]); acc[3][3] = fmaf(a4.w, b4.w, acc[3][3]);
        }
        __syncthreads();
    }
    #pragma unroll
    for (int i = 0; i < 4; i++) {
        int row = m0 + ty * 4 + i;
        #pragma unroll
        for (int j = 0; j < 4; j++) {
            int col = n0 + tx * 4 + j;
            float v = acc[i][j] + bias[col];
            if (MODE == 0) v = silu_f(v);
            C[(size_t)row * Nd + col] = v;
        }
    }
}

// ---------------- GraphNorm: deterministic per-graph column reductions ----
__global__ void k_gsum() {
    int g = blockIdx.x, chunk = blockIdx.y;
    int t = threadIdx.x;
    int cl = t & 31, seg = t >> 5;
    int c = chunk * 32 + cl;
    int base = g * NPG + seg * 64;
    float s = 0.f;
    for (int n = 0; n < 64; n++) s += d_z[(size_t)(base + n) * HH + c];
    __shared__ float red[8][32];
    red[seg][cl] = s;
    __syncthreads();
    if (seg == 0) {
        float tot = 0.f;
        #pragma unroll
        for (int q = 0; q < 8; q++) tot += red[q][cl];
        d_sumz[g * HH + c] = tot;
    }
}

__global__ void k_gvar(const float* __restrict__ gms) {
    int g = blockIdx.x, chunk = blockIdx.y;
    int t = threadIdx.x;
    int cl = t & 31, seg = t >> 5;
    int c = chunk * 32 + cl;
    float mean = d_sumz[g * HH + c] * (1.f / 512.f);
    float mm = mean * gms[c];
    int base = g * NPG + seg * 64;
    float s = 0.f;
    for (int n = 0; n < 64; n++) {
        float cc = d_z[(size_t)(base + n) * HH + c] - mm;
        s += cc * cc;
    }
    __shared__ float red[8][32];
    red[seg][cl] = s;
    __syncthreads();
    if (seg == 0) {
        float tot = 0.f;
        #pragma unroll
        for (int q = 0; q < 8; q++) tot += red[q][cl];
        d_sumc2[g * HH + c] = tot;
    }
}

__global__ void k_gfin(const float* __restrict__ gw, const float* __restrict__ gb,
                       const float* __restrict__ gms) {
    int nb = blockIdx.x * 64;
    int g = nb >> 9;
    int c = threadIdx.x;
    float mean = d_sumz[g * HH + c] * (1.f / 512.f);
    float var = d_sumc2[g * HH + c] * (1.f / 512.f);
    float mm = mean * gms[c];
    float inv = 1.f / sqrtf(var + 1e-5f);
    float w = gw[c], b = gb[c];
    for (int n = 0; n < 64; n++) {
        size_t id = (size_t)(nb + n) * HH + c;
        float cc = d_z[id] - mm;
        float zn = fmaf(w * cc, inv, b);
        float hv = zn + d_h[id];
        d_h[id] = silu_f(hv);
    }
}

// ---------------- output head: out = h @ W_out + b_out -------------------
__global__ void k_out(const float* __restrict__ Wout, const float* __restrict__ bout,
                      float* __restrict__ out) {
    __shared__ float sw[HH * 3];
    int t = threadIdx.x;
    for (int idx = t; idx < HH * 3; idx += 256) sw[idx] = Wout[idx];
    __syncthreads();
    int w = t >> 5, lane = t & 31;
    int i = blockIdx.x * 8 + w;
    float a0 = 0.f, a1 = 0.f, a2 = 0.f;
    for (int c = lane; c < HH; c += 32) {
        float hv = d_h[(size_t)i * HH + c];
        a0 = fmaf(hv, sw[c * 3 + 0], a0);
        a1 = fmaf(hv, sw[c * 3 + 1], a1);
        a2 = fmaf(hv, sw[c * 3 + 2], a2);
    }
    #pragma unroll
    for (int off = 16; off; off >>= 1) {
        a0 += __shfl_down_sync(0xffffffffu, a0, off);
        a1 += __shfl_down_sync(0xffffffffu, a1, off);
        a2 += __shfl_down_sync(0xffffffffu, a2, off);
    }
    if (lane == 0) {
        out[i * 3 + 0] = a0 + bout[0];
        out[i * 3 + 1] = a1 + bout[1];
        out[i * 3 + 2] = a2 + bout[2];
    }
}

// -------------------------------------------------------------------------
extern "C" void kernel_launch(void* const* d_in, const int* in_sizes, int n_in,
                              void* d_out, int out_size) {
    const float* coords = (const float*)d_in[0];
    // d_in[1]: batch (structure is implicit: contiguous 512-node graphs)
    const float* tin  = (const float*)d_in[2];
    const float* Wgfp = (const float*)d_in[3];
    const float* Wt_  = (const float*)d_in[4];
    const float* bt_  = (const float*)d_in[5];
    const float* Win  = (const float*)d_in[6];
    const float* bin  = (const float*)d_in[7];
    const float* W1   = (const float*)d_in[8];
    const float* b1   = (const float*)d_in[9];
    const float* W2   = (const float*)d_in[10];
    const float* b2   = (const float*)d_in[11];
    const float* We   = (const float*)d_in[12];
    const float* be   = (const float*)d_in[13];
    const float* eps  = (const float*)d_in[14];
    const float* gnw  = (const float*)d_in[15];
    const float* gnb  = (const float*)d_in[16];
    const float* gnms = (const float*)d_in[17];
    const float* Wtl  = (const float*)d_in[18];
    const float* btl  = (const float*)d_in[19];
    const float* Wout = (const float*)d_in[20];
    const float* bout = (const float*)d_in[21];
    float* out = (float*)d_out;

    k_temb<<<1, 128>>>(tin, Wgfp, Wt_, bt_);
    k_tproj<<<LL * BB, 256>>>(Wtl, btl);
    k_hin<<<NN, 256>>>(coords, Win, bin);
    k_nbr<<<NN / 4, 128>>>(coords);
    k_eattr<<<(NN * KK + 127) / 128, 128>>>(coords);

    for (int l = 0; l < LL; l++) {
        k_x<<<NN * X2H / 256, 256>>>(l);
        k_edge<<<NN, 256>>>(We + (size_t)l * EDIM * X2H, be + l * X2H);
        k_gemm<0><<<dim3(4, 64), 256>>>(W1 + (size_t)l * X2H * HH, b1 + l * HH, eps, l);
        k_gemm<1><<<dim3(4, 64), 256>>>(W2 + (size_t)l * HH * HH, b2 + l * HH, eps, l);
        k_gsum<<<dim3(BB, 8), 256>>>();
        k_gvar<<<dim3(BB, 8), 256>>>(gnms + l * HH);
        k_gfin<<<64, 256>>>(gnw + l * HH, gnb + l * HH, gnms + l * HH);
    }
    k_out<<<NN / 8, 256>>>(Wout, bout, out);
}